// round 4
// baseline (speedup 1.0000x reference)
#include <cuda_runtime.h>
#include <math.h>
#include <stddef.h>

#define DIMD   256
#define NBATCH 64
#define NTOK   4096
#define NS     8
#define MROWS  (NBATCH*NS)          // 512
#define NROWS  ((size_t)NBATCH*NTOK) // 262144
#define NCH    16                   // chunks per batch
#define CROWS  (NTOK/NCH)           // 256 rows per block
#define SCALE  0.0625f
#define EPSLN  1e-5f
#define SREN   (1.0f + 4096.0f*1e-8f)

// ------------------------- static device scratch -------------------------
__device__ float2 d_stats[NROWS];
__device__ float  d_PC [NBATCH*NCH*DIMD];
__device__ float  d_PCt[NBATCH*NCH];
__device__ float  d_Cx [NBATCH*DIMD];
__device__ float  d_Ct [NBATCH];
__device__ float  d_PV [(size_t)NBATCH*NCH*NS*DIMD];
__device__ float  d_Pl [NBATCH*NCH*NS];
__device__ float  d_Pt [NBATCH*NCH*NS];
__device__ float  d_Avec[MROWS*DIMD];
__device__ float  d_Gc [MROWS];
__device__ float  d_Bc [MROWS];
__device__ float  d_Mm [DIMD*DIMD];
__device__ float  d_Wihv[3*DIMD*DIMD];
__device__ float  d_S   [MROWS*DIMD];
__device__ float  d_lnb [MROWS*DIMD];   // LN buffer (slot-LN / ff-LN)
__device__ float  d_Upre[MROWS*DIMD];
__device__ float  d_hff [MROWS*DIMD];
__device__ float  d_gi  [MROWS*3*DIMD];
__device__ float  d_gh  [MROWS*3*DIMD];

__device__ __forceinline__ float wsum(float v){
#pragma unroll
    for (int o = 16; o > 0; o >>= 1) v += __shfl_xor_sync(0xffffffffu, v, o);
    return v;
}

// ---------------- precompute M = Wq^T @ Wk ----------------
__global__ void k_precM(const float* __restrict__ Wq, const float* __restrict__ Wk){
    int dd = blockIdx.x, t = threadIdx.x;
    float acc = 0.f;
    for (int e = 0; e < DIMD; e++)
        acc = fmaf(Wq[e*DIMD + dd], Wk[e*DIMD + t], acc);
    d_Mm[dd*DIMD + t] = acc;
}

// ---------------- precompute Wihv = W_ih @ Wv ----------------
__global__ void k_precWihv(const float* __restrict__ Wih, const float* __restrict__ Wv){
    int j = blockIdx.x, t = threadIdx.x;
    float acc = 0.f;
    for (int d = 0; d < DIMD; d++)
        acc = fmaf(Wih[j*DIMD + d], Wv[d*DIMD + t], acc);
    d_Wihv[j*DIMD + t] = acc;
}

// ---------------- initial slots ----------------
__global__ void k_init(const float* __restrict__ mu, const float* __restrict__ noise,
                       const float* __restrict__ ls){
    int m = blockIdx.x, t = threadIdx.x;
    d_S[m*DIMD + t] = fmaf(noise[m*DIMD + t], __expf(ls[t]), mu[t]);
}

// ---------------- per-row LN stats of x + per-batch column sums ----------------
__global__ void k_stats(const float* __restrict__ x){
    int b = blockIdx.y, c = blockIdx.x;
    int w = threadIdx.x >> 5, lane = threadIdx.x & 31;
    float Cacc[8]; float ctacc = 0.f;
#pragma unroll
    for (int j = 0; j < 8; j++) Cacc[j] = 0.f;

    for (int r = 0; r < 32; r++){
        size_t n = (size_t)b*NTOK + (size_t)c*CROWS + w*32 + r;
        const float* xr = x + n*DIMD + lane*8;
        float4 xa = *(const float4*)xr;
        float4 xb = *(const float4*)(xr + 4);
        float v[8] = {xa.x,xa.y,xa.z,xa.w,xb.x,xb.y,xb.z,xb.w};
        float s = 0.f, q = 0.f;
#pragma unroll
        for (int j = 0; j < 8; j++){ s += v[j]; q = fmaf(v[j], v[j], q); }
        s = wsum(s); q = wsum(q);
        float mu  = s * (1.0f/DIMD);
        float var = q * (1.0f/DIMD) - mu*mu;
        float rs  = rsqrtf(var + EPSLN);
        if (lane == 0) d_stats[n] = make_float2(mu, rs);
#pragma unroll
        for (int j = 0; j < 8; j++) Cacc[j] = fmaf(rs, v[j], Cacc[j]);
        ctacc = fmaf(mu, rs, ctacc);
    }
    __shared__ float sh[8][DIMD];
    __shared__ float cts[8];
#pragma unroll
    for (int j = 0; j < 8; j++) sh[w][lane*8 + j] = Cacc[j];
    if (lane == 0) cts[w] = ctacc;
    __syncthreads();
    int t = threadIdx.x;
    float a = 0.f;
#pragma unroll
    for (int ww = 0; ww < 8; ww++) a += sh[ww][t];
    d_PC[((size_t)b*NCH + c)*DIMD + t] = a;
    if (t == 0){
        float s2 = 0.f;
        for (int ww = 0; ww < 8; ww++) s2 += cts[ww];
        d_PCt[b*NCH + c] = s2;
    }
}

__global__ void k_redC(){
    int b = blockIdx.x, t = threadIdx.x;
    float a = 0.f;
    for (int c = 0; c < NCH; c++) a += d_PC[((size_t)b*NCH + c)*DIMD + t];
    d_Cx[b*DIMD + t] = a;
    if (t == 0){
        float s = 0.f;
        for (int c = 0; c < NCH; c++) s += d_PCt[b*NCH + c];
        d_Ct[b] = s;
    }
}

// ---------------- LN of 512 rows (warp per row) ----------------
__global__ void k_lnrow(const float* __restrict__ in, float* __restrict__ out,
                        const float* __restrict__ g, const float* __restrict__ be){
    int w = (blockIdx.x * blockDim.x + threadIdx.x) >> 5;
    int lane = threadIdx.x & 31;
    const float* row = in + (size_t)w*DIMD + lane*8;
    float4 xa = *(const float4*)row;
    float4 xb = *(const float4*)(row + 4);
    float v[8] = {xa.x,xa.y,xa.z,xa.w,xb.x,xb.y,xb.z,xb.w};
    float s = 0.f, q = 0.f;
#pragma unroll
    for (int j = 0; j < 8; j++){ s += v[j]; q = fmaf(v[j], v[j], q); }
    s = wsum(s); q = wsum(q);
    float mu = s * (1.0f/DIMD);
    float rs = rsqrtf(q * (1.0f/DIMD) - mu*mu + EPSLN);
    float* orow = out + (size_t)w*DIMD;
#pragma unroll
    for (int j = 0; j < 8; j++){
        int dd = lane*8 + j;
        orow[dd] = (v[j] - mu)*rs*g[dd] + be[dd];
    }
}

// ---------------- prep: A_s, G_s, B_s from LN(slots) ----------------
__global__ void k_prep(const float* __restrict__ gin, const float* __restrict__ bein){
    int m = blockIdx.x, t = threadIdx.x;
    __shared__ float sl[DIMD];
    __shared__ float red[DIMD];
    sl[t] = d_lnb[m*DIMD + t];
    __syncthreads();
    float cacc = 0.f;
    for (int d = 0; d < DIMD; d++) cacc = fmaf(sl[d], d_Mm[d*DIMD + t], cacc);
    float Av = SCALE * gin[t] * cacc;
    d_Avec[m*DIMD + t] = Av;
    red[t] = Av; __syncthreads();
    for (int o = 128; o > 0; o >>= 1){ if (t < o) red[t] += red[t + o]; __syncthreads(); }
    if (t == 0) d_Gc[m] = red[0];
    __syncthreads();
    red[t] = SCALE * bein[t] * cacc; __syncthreads();
    for (int o = 128; o > 0; o >>= 1){ if (t < o) red[t] += red[t + o]; __syncthreads(); }
    if (t == 0) d_Bc[m] = red[0];
}

// ---------------- flash pass: softmax-accumulate over raw x ----------------
__global__ void __launch_bounds__(256) k_flash(const float* __restrict__ x){
    int b = blockIdx.y, c = blockIdx.x;
    int w = threadIdx.x >> 5, lane = threadIdx.x & 31;

    float Areg[NS][8];
#pragma unroll
    for (int s = 0; s < NS; s++){
        const float* Ap = d_Avec + ((size_t)(b*NS + s))*DIMD + lane*8;
        float4 u0 = *(const float4*)Ap;
        float4 u1 = *(const float4*)(Ap + 4);
        Areg[s][0]=u0.x; Areg[s][1]=u0.y; Areg[s][2]=u0.z; Areg[s][3]=u0.w;
        Areg[s][4]=u1.x; Areg[s][5]=u1.y; Areg[s][6]=u1.z; Areg[s][7]=u1.w;
    }
    float Gr[NS], Br[NS];
#pragma unroll
    for (int s = 0; s < NS; s++){ Gr[s] = d_Gc[b*NS + s]; Br[s] = d_Bc[b*NS + s]; }

    float V[NS][8];
    float lacc[NS], tacc[NS];
#pragma unroll
    for (int s = 0; s < NS; s++){
        lacc[s] = 0.f; tacc[s] = 0.f;
#pragma unroll
        for (int j = 0; j < 8; j++) V[s][j] = 0.f;
    }

    for (int r = 0; r < 32; r++){
        size_t n = (size_t)b*NTOK + (size_t)c*CROWS + w*32 + r;
        const float* xr = x + n*DIMD + lane*8;
        float4 xa = *(const float4*)xr;
        float4 xb = *(const float4*)(xr + 4);
        float xv[8] = {xa.x,xa.y,xa.z,xa.w,xb.x,xb.y,xb.z,xb.w};
        float2 st = d_stats[n];
        float mu = st.x, rs = st.y;

        float p[NS];
#pragma unroll
        for (int s = 0; s < NS; s++){
            float a = 0.f;
#pragma unroll
            for (int j = 0; j < 8; j++) a = fmaf(xv[j], Areg[s][j], a);
            p[s] = a;
        }
#pragma unroll
        for (int o = 16; o > 0; o >>= 1){
#pragma unroll
            for (int s = 0; s < NS; s++) p[s] += __shfl_xor_sync(0xffffffffu, p[s], o);
        }
        float murs = mu * rs;
        float ws[NS];
#pragma unroll
        for (int s = 0; s < NS; s++){
            float l = fmaf(rs, p[s], fmaf(-murs, Gr[s], Br[s]));
            float e = __expf(l);
            ws[s] = e;
            lacc[s] += e;
            tacc[s] = fmaf(e, murs, tacc[s]);
        }
        float y[8];
#pragma unroll
        for (int j = 0; j < 8; j++) y[j] = rs * xv[j];
#pragma unroll
        for (int s = 0; s < NS; s++){
#pragma unroll
            for (int j = 0; j < 8; j++) V[s][j] = fmaf(ws[s], y[j], V[s][j]);
        }
    }

    __shared__ float sh[8][DIMD];
    __shared__ float lsh[8][NS], tsh[8][NS];
    size_t pbase = ((size_t)(b*NCH + c)) * NS;
    int t = threadIdx.x;
    for (int s = 0; s < NS; s++){
#pragma unroll
        for (int j = 0; j < 8; j++) sh[w][lane*8 + j] = V[s][j];
        __syncthreads();
        float a = 0.f;
#pragma unroll
        for (int ww = 0; ww < 8; ww++) a += sh[ww][t];
        d_PV[(pbase + s)*DIMD + t] = a;
        __syncthreads();
    }
    if (lane == 0){
#pragma unroll
        for (int s = 0; s < NS; s++){ lsh[w][s] = lacc[s]; tsh[w][s] = tacc[s]; }
    }
    __syncthreads();
    if (t < NS){
        float a = 0.f, bb = 0.f;
#pragma unroll
        for (int ww = 0; ww < 8; ww++){ a += lsh[ww][t]; bb += tsh[ww][t]; }
        d_Pl[pbase + t] = a;
        d_Pt[pbase + t] = bb;
    }
}

// ---------------- combine partials -> Upre ----------------
__global__ void k_combine(const float* __restrict__ gin, const float* __restrict__ bein){
    int m = blockIdx.x, t = threadIdx.x;
    int b = m >> 3, s = m & 7;
    float Z = 0.f, tr = 0.f, Vr = 0.f;
    for (int c = 0; c < NCH; c++){
        size_t pbase = ((size_t)(b*NCH + c)) * NS + s;
        Z  += d_Pl[pbase];
        tr += d_Pt[pbase];
        Vr += d_PV[pbase*DIMD + t];
    }
    float invZ = 1.0f / Z;
    float Vn = (Vr*invZ + 1e-8f*d_Cx[b*DIMD + t]) * (1.0f/SREN);
    float tn = (tr*invZ + 1e-8f*d_Ct[b]) * (1.0f/SREN);
    d_Upre[m*DIMD + t] = fmaf(gin[t], Vn - tn, bein[t]);
}

// ---------------- small SGEMM: C[M,N] = act(A[M,K=256] @ B[N,K]^T + bias) (+resid)
// block: 256 threads, 32x32 tile, 2x2 per thread
__global__ void k_gemm(const float* __restrict__ A, const float* __restrict__ B,
                       const float* __restrict__ bias, const float* __restrict__ resid,
                       float* __restrict__ C, int Nc, int act){
    __shared__ float As[16][33];
    __shared__ float Bs[16][33];
    int tid = threadIdx.x;
    int tx = tid & 15, ty = tid >> 4;
    int m0 = blockIdx.y * 32, n0 = blockIdx.x * 32;
    float a00 = 0.f, a01 = 0.f, a10 = 0.f, a11 = 0.f;
    for (int k0 = 0; k0 < DIMD; k0 += 16){
#pragma unroll
        for (int i = 0; i < 2; i++){
            int idx = tid + i*256;
            int kk = idx & 15, mm = idx >> 4;
            As[kk][mm] = A[(size_t)(m0 + mm)*DIMD + k0 + kk];
            Bs[kk][mm] = B[(size_t)(n0 + mm)*DIMD + k0 + kk];
        }
        __syncthreads();
#pragma unroll
        for (int kk = 0; kk < 16; kk++){
            float av0 = As[kk][ty*2], av1 = As[kk][ty*2 + 1];
            float bv0 = Bs[kk][tx*2], bv1 = Bs[kk][tx*2 + 1];
            a00 = fmaf(av0, bv0, a00); a01 = fmaf(av0, bv1, a01);
            a10 = fmaf(av1, bv0, a10); a11 = fmaf(av1, bv1, a11);
        }
        __syncthreads();
    }
    int m = m0 + ty*2, n = n0 + tx*2;
    float vals[2][2] = {{a00, a01}, {a10, a11}};
#pragma unroll
    for (int i = 0; i < 2; i++){
#pragma unroll
        for (int j = 0; j < 2; j++){
            float v = vals[i][j] + bias[n + j];
            if (act == 1) v = fmaxf(v, 0.f);
            if (resid) v += resid[(size_t)(m + i)*Nc + n + j];
            C[(size_t)(m + i)*Nc + n + j] = v;
        }
    }
}

// ---------------- GRU gates ----------------
__global__ void k_gate(){
    int m = blockIdx.x, t = threadIdx.x;
    const float* gi = d_gi + (size_t)m*768;
    const float* gh = d_gh + (size_t)m*768;
    float ir = gi[t],       hr = gh[t];
    float iz = gi[256 + t], hz = gh[256 + t];
    float in_ = gi[512 + t], hn = gh[512 + t];
    float r = 1.0f / (1.0f + __expf(-(ir + hr)));
    float z = 1.0f / (1.0f + __expf(-(iz + hz)));
    float nn = tanhf(fmaf(r, hn, in_));
    float h = d_S[(size_t)m*DIMD + t];
    d_S[(size_t)m*DIMD + t] = fmaf(1.0f - z, nn, z * h);
}

// ---------------- launch ----------------
extern "C" void kernel_launch(void* const* d_in, const int* in_sizes, int n_in,
                              void* d_out, int out_size){
    const float* x      = (const float*)d_in[0];
    const float* noise  = (const float*)d_in[1];
    const float* smu    = (const float*)d_in[2];
    const float* slsig  = (const float*)d_in[3];
    const float* Wq     = (const float*)d_in[4];
    const float* Wk     = (const float*)d_in[5];
    const float* Wv     = (const float*)d_in[6];
    const float* Wih    = (const float*)d_in[7];
    const float* Whh    = (const float*)d_in[8];
    const float* bih    = (const float*)d_in[9];
    const float* bhh    = (const float*)d_in[10];
    const float* W1     = (const float*)d_in[11];
    const float* b1     = (const float*)d_in[12];
    const float* W2     = (const float*)d_in[13];
    const float* b2     = (const float*)d_in[14];
    const float* g_in   = (const float*)d_in[15];
    const float* be_in  = (const float*)d_in[16];
    const float* g_sl   = (const float*)d_in[17];
    const float* be_sl  = (const float*)d_in[18];
    const float* g_ff   = (const float*)d_in[19];
    const float* be_ff  = (const float*)d_in[20];
    float* out = (float*)d_out;

    float *dS, *dLn, *dUpre, *dHff, *dGi, *dGh;
    cudaGetSymbolAddress((void**)&dS,    d_S);
    cudaGetSymbolAddress((void**)&dLn,   d_lnb);
    cudaGetSymbolAddress((void**)&dUpre, d_Upre);
    cudaGetSymbolAddress((void**)&dHff,  d_hff);
    cudaGetSymbolAddress((void**)&dGi,   d_gi);
    cudaGetSymbolAddress((void**)&dGh,   d_gh);
    float *dWihv;
    cudaGetSymbolAddress((void**)&dWihv, d_Wihv);

    k_precM   <<<DIMD,   DIMD>>>(Wq, Wk);
    k_precWihv<<<3*DIMD, DIMD>>>(Wih, Wv);
    k_init    <<<MROWS,  DIMD>>>(smu, noise, slsig);
    k_stats   <<<dim3(NCH, NBATCH), 256>>>(x);
    k_redC    <<<NBATCH, DIMD>>>();

    for (int it = 0; it < 3; it++){
        k_lnrow  <<<MROWS/8, 256>>>(dS, dLn, g_sl, be_sl);
        k_prep   <<<MROWS, DIMD>>>(g_in, be_in);
        k_flash  <<<dim3(NCH, NBATCH), 256>>>(x);
        k_combine<<<MROWS, DIMD>>>(g_in, be_in);
        // gi = Upre @ Wihv^T + b_ih ; gh = S @ W_hh^T + b_hh
        k_gemm<<<dim3(768/32, MROWS/32), 256>>>(dUpre, dWihv, bih, nullptr, dGi, 768, 0);
        k_gemm<<<dim3(768/32, MROWS/32), 256>>>(dS,    Whh,   bhh, nullptr, dGh, 768, 0);
        k_gate<<<MROWS, DIMD>>>();
        // FF block
        k_lnrow<<<MROWS/8, 256>>>(dS, dLn, g_ff, be_ff);
        k_gemm<<<dim3(DIMD/32, MROWS/32), 256>>>(dLn, W1, b1, nullptr, dHff, DIMD, 1);
        float* dst = (it == 2) ? out : dS;
        k_gemm<<<dim3(DIMD/32, MROWS/32), 256>>>(dHff, W2, b2, dS, dst, DIMD, 0);
    }
    (void)in_sizes; (void)n_in; (void)out_size;
}

// round 5
// speedup vs baseline: 1.3404x; 1.3404x over previous
#include <cuda_runtime.h>
#include <math.h>
#include <stddef.h>

#define DIMD   256
#define NBATCH 64
#define NTOK   4096
#define NS     8
#define MROWS  (NBATCH*NS)           // 512
#define NROWS  ((size_t)NBATCH*NTOK) // 262144
#define NCH    32                    // chunks per batch (flash)
#define CROWS  (NTOK/NCH)            // 128 rows per flash block
#define SCALE  0.0625f
#define EPSLN  1e-5f
#define SREN   (1.0f + 4096.0f*1e-8f)

typedef unsigned long long ull;

// ------------------------- static device scratch -------------------------
__device__ float2 d_stats[NROWS];
__device__ float  d_PC [NBATCH*NCH*DIMD];
__device__ float  d_PCt[NBATCH*NCH];
__device__ float  d_Cx [NBATCH*DIMD];
__device__ float  d_Ct [NBATCH];
__device__ float  d_PV [(size_t)NBATCH*NCH*NS*DIMD];
__device__ float  d_Pl [NBATCH*NCH*NS];
__device__ float  d_Pt [NBATCH*NCH*NS];
__device__ float  d_Avec[MROWS*DIMD];
__device__ float  d_Apre[MROWS*DIMD];
__device__ float  d_Gc [MROWS];
__device__ float  d_Bc [MROWS];
__device__ float  d_Mm [DIMD*DIMD];      // (Wq^T Wk)^T  i.e. Mm[t][d] = M[d][t]
__device__ float  d_Wihv[3*DIMD*DIMD];
__device__ float  d_S   [MROWS*DIMD];
__device__ float  d_lnb [MROWS*DIMD];
__device__ float  d_Upre[MROWS*DIMD];
__device__ float  d_hff [MROWS*DIMD];
__device__ float  d_gi  [MROWS*3*DIMD];
__device__ float  d_gh  [MROWS*3*DIMD];

// ------------------------- packed f32x2 helpers -------------------------
__device__ __forceinline__ ull pk2(float lo, float hi){
    ull r; asm("mov.b64 %0, {%1, %2};" : "=l"(r) : "f"(lo), "f"(hi)); return r;
}
__device__ __forceinline__ void upk2(float& lo, float& hi, ull v){
    asm("mov.b64 {%0, %1}, %2;" : "=f"(lo), "=f"(hi) : "l"(v));
}
__device__ __forceinline__ ull fma2(ull a, ull b, ull c){
    ull d; asm("fma.rn.f32x2 %0, %1, %2, %3;" : "=l"(d) : "l"(a), "l"(b), "l"(c)); return d;
}
__device__ __forceinline__ ull mul2(ull a, ull b){
    ull d; asm("mul.rn.f32x2 %0, %1, %2;" : "=l"(d) : "l"(a), "l"(b)); return d;
}
__device__ __forceinline__ ull add2(ull a, ull b){
    ull d; asm("add.rn.f32x2 %0, %1, %2;" : "=l"(d) : "l"(a), "l"(b)); return d;
}

__device__ __forceinline__ float wsum(float v){
#pragma unroll
    for (int o = 16; o > 0; o >>= 1) v += __shfl_xor_sync(0xffffffffu, v, o);
    return v;
}

// ---------------- precompute (Wq^T Wk), stored transposed ----------------
__global__ void k_precM(const float* __restrict__ Wq, const float* __restrict__ Wk){
    int dd = blockIdx.x, t = threadIdx.x;
    float acc = 0.f;
    for (int e = 0; e < DIMD; e++)
        acc = fmaf(Wq[e*DIMD + dd], Wk[e*DIMD + t], acc);
    d_Mm[t*DIMD + dd] = acc;   // transposed store: Mm[t][dd] = M[dd][t]
}

// ---------------- precompute Wihv = W_ih @ Wv ----------------
__global__ void k_precWihv(const float* __restrict__ Wih, const float* __restrict__ Wv){
    int j = blockIdx.x, t = threadIdx.x;
    float acc = 0.f;
    for (int d = 0; d < DIMD; d++)
        acc = fmaf(Wih[j*DIMD + d], Wv[d*DIMD + t], acc);
    d_Wihv[j*DIMD + t] = acc;
}

// ---------------- initial slots ----------------
__global__ void k_init(const float* __restrict__ mu, const float* __restrict__ noise,
                       const float* __restrict__ ls){
    int m = blockIdx.x, t = threadIdx.x;
    d_S[m*DIMD + t] = fmaf(noise[m*DIMD + t], __expf(ls[t]), mu[t]);
}

// ---------------- LN of 512 rows (warp per row) ----------------
__global__ void k_lnrow(const float* __restrict__ in, float* __restrict__ out,
                        const float* __restrict__ g, const float* __restrict__ be){
    int w = (blockIdx.x * blockDim.x + threadIdx.x) >> 5;
    int lane = threadIdx.x & 31;
    const float* row = in + (size_t)w*DIMD + lane*8;
    float4 xa = *(const float4*)row;
    float4 xb = *(const float4*)(row + 4);
    float v[8] = {xa.x,xa.y,xa.z,xa.w,xb.x,xb.y,xb.z,xb.w};
    float s = 0.f, q = 0.f;
#pragma unroll
    for (int j = 0; j < 8; j++){ s += v[j]; q = fmaf(v[j], v[j], q); }
    s = wsum(s); q = wsum(q);
    float mu = s * (1.0f/DIMD);
    float rs = rsqrtf(q * (1.0f/DIMD) - mu*mu + EPSLN);
    float* orow = out + (size_t)w*DIMD;
#pragma unroll
    for (int j = 0; j < 8; j++){
        int dd = lane*8 + j;
        orow[dd] = (v[j] - mu)*rs*g[dd] + be[dd];
    }
}

// ---------------- finalize A_s, G_s, B_s from Apre = LN(slots)@M ----------------
__global__ void k_finA(const float* __restrict__ gin, const float* __restrict__ bein){
    int m = blockIdx.x, t = threadIdx.x;
    float cv = d_Apre[m*DIMD + t];
    float Av = SCALE * gin[t] * cv;
    d_Avec[m*DIMD + t] = Av;
    __shared__ float r1[DIMD], r2[DIMD];
    r1[t] = Av;
    r2[t] = SCALE * bein[t] * cv;
    __syncthreads();
    for (int o = 128; o > 0; o >>= 1){
        if (t < o){ r1[t] += r1[t+o]; r2[t] += r2[t+o]; }
        __syncthreads();
    }
    if (t == 0){ d_Gc[m] = r1[0]; d_Bc[m] = r2[0]; }
}

// ---------------- flash pass ----------------
// 128 threads (4 warps), 128 rows per block. Lane group g = lane>>2 owns slot g.
// Per-lane arrays permuted: index j <-> real slot (g ^ j), so all register
// indices stay static through the XOR-butterfly.
template<bool FIRST>
__global__ void __launch_bounds__(128,3) k_flash(const float* __restrict__ x){
    int b = blockIdx.y, c = blockIdx.x;
    int w = threadIdx.x >> 5, lane = threadIdx.x & 31;
    int g = lane >> 2;

    ull Ap[NS][4];
#pragma unroll
    for (int j = 0; j < NS; j++){
        int s = g ^ j;
        const float* p = d_Avec + (size_t)(b*NS + s)*DIMD + lane*8;
        float4 u0 = *(const float4*)p;
        float4 u1 = *(const float4*)(p + 4);
        Ap[j][0] = pk2(u0.x,u0.y); Ap[j][1] = pk2(u0.z,u0.w);
        Ap[j][2] = pk2(u1.x,u1.y); Ap[j][3] = pk2(u1.z,u1.w);
    }
    float Gs = d_Gc[b*NS + g], Bs = d_Bc[b*NS + g];

    ull V[NS][4];
#pragma unroll
    for (int j = 0; j < NS; j++){
#pragma unroll
        for (int k = 0; k < 4; k++) V[j][k] = 0ull;
    }
    float lacc = 0.f, tacc = 0.f;
    ull Cp[4] = {0ull,0ull,0ull,0ull};
    float ct = 0.f;

    for (int r = 0; r < 32; r++){
        size_t n = (size_t)b*NTOK + (size_t)c*CROWS + w*32 + r;
        const float* xr = x + n*DIMD + lane*8;
        float4 xa = *(const float4*)xr;
        float4 xb = *(const float4*)(xr + 4);
        ull xp[4] = { pk2(xa.x,xa.y), pk2(xa.z,xa.w), pk2(xb.x,xb.y), pk2(xb.z,xb.w) };

        float mu, rs;
        if (FIRST){
            ull sp = add2(add2(xp[0],xp[1]), add2(xp[2],xp[3]));
            ull qp = fma2(xp[0],xp[0], fma2(xp[1],xp[1], fma2(xp[2],xp[2], mul2(xp[3],xp[3]))));
            float s0,s1,q0,q1; upk2(s0,s1,sp); upk2(q0,q1,qp);
            float s = wsum(s0 + s1);
            float q = wsum(q0 + q1);
            mu = s * (1.0f/DIMD);
            rs = rsqrtf(q * (1.0f/DIMD) - mu*mu + EPSLN);
            if (lane == 0) d_stats[n] = make_float2(mu, rs);
            ull rsp = pk2(rs, rs);
#pragma unroll
            for (int k = 0; k < 4; k++) Cp[k] = fma2(rsp, xp[k], Cp[k]);
            ct = fmaf(mu, rs, ct);
        } else {
            float2 st = d_stats[n];
            mu = st.x; rs = st.y;
        }

        // partial dots, permuted: p[j] = <x_lane_dims, A_slot(g^j)>
        float p[NS];
#pragma unroll
        for (int j = 0; j < NS; j++){
            ull acc = fma2(Ap[j][0], xp[0],
                      fma2(Ap[j][1], xp[1],
                      fma2(Ap[j][2], xp[2],
                      mul2(Ap[j][3], xp[3]))));
            float lo, hi; upk2(lo, hi, acc);
            p[j] = lo + hi;
        }
        // XOR-butterfly reduce-scatter: after this, p[0] = full dot of slot g
        p[0] += __shfl_xor_sync(0xffffffffu, p[4], 16);
        p[1] += __shfl_xor_sync(0xffffffffu, p[5], 16);
        p[2] += __shfl_xor_sync(0xffffffffu, p[6], 16);
        p[3] += __shfl_xor_sync(0xffffffffu, p[7], 16);
        p[0] += __shfl_xor_sync(0xffffffffu, p[2], 8);
        p[1] += __shfl_xor_sync(0xffffffffu, p[3], 8);
        p[0] += __shfl_xor_sync(0xffffffffu, p[1], 4);
        p[0] += __shfl_xor_sync(0xffffffffu, p[0], 2);
        p[0] += __shfl_xor_sync(0xffffffffu, p[0], 1);

        float murs = mu * rs;
        float lg = fmaf(rs, p[0], fmaf(-murs, Gs, Bs));
        float e = __expf(lg);
        lacc += e;
        tacc = fmaf(e, murs, tacc);

        // allgather weights (pre-scaled by rs), permuted: aa[j] = w_{slot g^j} * rs
        float a0 = e * rs;
        float a1 = __shfl_xor_sync(0xffffffffu, a0, 4);
        float a2 = __shfl_xor_sync(0xffffffffu, a0, 8);
        float a3 = __shfl_xor_sync(0xffffffffu, a1, 8);
        float a4 = __shfl_xor_sync(0xffffffffu, a0, 16);
        float a5 = __shfl_xor_sync(0xffffffffu, a1, 16);
        float a6 = __shfl_xor_sync(0xffffffffu, a2, 16);
        float a7 = __shfl_xor_sync(0xffffffffu, a3, 16);
        float aa[NS] = {a0,a1,a2,a3,a4,a5,a6,a7};
#pragma unroll
        for (int j = 0; j < NS; j++){
            ull ap = pk2(aa[j], aa[j]);
#pragma unroll
            for (int k = 0; k < 4; k++) V[j][k] = fma2(ap, xp[k], V[j][k]);
        }
    }

    // ---------------- epilogue ----------------
    __shared__ float shV[4][NS][DIMD];      // 32 KB
    __shared__ float shl[4][NS], sht[4][NS];
    __shared__ float shC[4][DIMD];
    __shared__ float shct[4];
#pragma unroll
    for (int j = 0; j < NS; j++){
        int s = g ^ j;
        float2* dst = (float2*)&shV[w][s][lane*8];
#pragma unroll
        for (int k = 0; k < 4; k++){
            float lo, hi; upk2(lo, hi, V[j][k]);
            dst[k] = make_float2(lo, hi);
        }
    }
    if ((lane & 3) == 0){ shl[w][g] = lacc; sht[w][g] = tacc; }
    if (FIRST){
        float2* cd = (float2*)&shC[w][lane*8];
#pragma unroll
        for (int k = 0; k < 4; k++){
            float lo, hi; upk2(lo, hi, Cp[k]);
            cd[k] = make_float2(lo, hi);
        }
        if (lane == 0) shct[w] = ct;
    }
    __syncthreads();

    int t = threadIdx.x;
    size_t pbase = ((size_t)(b*NCH + c)) * NS;
#pragma unroll
    for (int i = 0; i < 16; i++){
        int idx = t + i*128;
        int s = idx >> 8, d = idx & 255;
        float a = shV[0][s][d] + shV[1][s][d] + shV[2][s][d] + shV[3][s][d];
        d_PV[(pbase + s)*DIMD + d] = a;
    }
    if (t < NS){
        d_Pl[pbase + t] = shl[0][t] + shl[1][t] + shl[2][t] + shl[3][t];
        d_Pt[pbase + t] = sht[0][t] + sht[1][t] + sht[2][t] + sht[3][t];
    }
    if (FIRST){
#pragma unroll
        for (int i = 0; i < 2; i++){
            int d = t + i*128;
            d_PC[((size_t)(b*NCH + c))*DIMD + d] =
                shC[0][d] + shC[1][d] + shC[2][d] + shC[3][d];
        }
        if (t == 0)
            d_PCt[b*NCH + c] = shct[0] + shct[1] + shct[2] + shct[3];
    }
}

// ---------------- reduce Cx over chunks (once) ----------------
__global__ void k_redC(){
    int b = blockIdx.x, t = threadIdx.x;
    float a = 0.f;
    for (int c = 0; c < NCH; c++) a += d_PC[((size_t)b*NCH + c)*DIMD + t];
    d_Cx[b*DIMD + t] = a;
    if (t == 0){
        float s = 0.f;
        for (int c = 0; c < NCH; c++) s += d_PCt[b*NCH + c];
        d_Ct[b] = s;
    }
}

// ---------------- combine partials -> Upre ----------------
__global__ void k_combine(const float* __restrict__ gin, const float* __restrict__ bein){
    int m = blockIdx.x, t = threadIdx.x;
    int b = m >> 3, s = m & 7;
    float Z = 0.f, tr = 0.f, Vr = 0.f;
    for (int c = 0; c < NCH; c++){
        size_t pb = ((size_t)(b*NCH + c)) * NS + s;
        Z  += d_Pl[pb];
        tr += d_Pt[pb];
        Vr += d_PV[pb*DIMD + t];
    }
    float invZ = 1.0f / Z;
    float Vn = (Vr*invZ + 1e-8f*d_Cx[b*DIMD + t]) * (1.0f/SREN);
    float tn = (tr*invZ + 1e-8f*d_Ct[b]) * (1.0f/SREN);
    d_Upre[m*DIMD + t] = fmaf(gin[t], Vn - tn, bein[t]);
}

// ---------------- small SGEMM: C = act(A @ B^T + bias) (+resid)
// 32x32 tile, 2x2 per thread; optional second problem via blockIdx.z
__global__ void k_gemm(const float* __restrict__ A, const float* __restrict__ B,
                       const float* __restrict__ bias, const float* __restrict__ resid,
                       float* __restrict__ C, int Nc, int act,
                       const float* __restrict__ A2, const float* __restrict__ B2,
                       const float* __restrict__ bias2, float* __restrict__ C2){
    if (blockIdx.z == 1){ A = A2; B = B2; bias = bias2; C = C2; resid = nullptr; }
    __shared__ float As[16][33];
    __shared__ float Bs[16][33];
    int tid = threadIdx.x;
    int tx = tid & 15, ty = tid >> 4;
    int m0 = blockIdx.y * 32, n0 = blockIdx.x * 32;
    float a00 = 0.f, a01 = 0.f, a10 = 0.f, a11 = 0.f;
    for (int k0 = 0; k0 < DIMD; k0 += 16){
#pragma unroll
        for (int i = 0; i < 2; i++){
            int idx = tid + i*256;
            int kk = idx & 15, mm = idx >> 4;
            As[kk][mm] = A[(size_t)(m0 + mm)*DIMD + k0 + kk];
            Bs[kk][mm] = B[(size_t)(n0 + mm)*DIMD + k0 + kk];
        }
        __syncthreads();
#pragma unroll
        for (int kk = 0; kk < 16; kk++){
            float av0 = As[kk][ty*2], av1 = As[kk][ty*2 + 1];
            float bv0 = Bs[kk][tx*2], bv1 = Bs[kk][tx*2 + 1];
            a00 = fmaf(av0, bv0, a00); a01 = fmaf(av0, bv1, a01);
            a10 = fmaf(av1, bv0, a10); a11 = fmaf(av1, bv1, a11);
        }
        __syncthreads();
    }
    int m = m0 + ty*2, n = n0 + tx*2;
    float vals[2][2] = {{a00, a01}, {a10, a11}};
#pragma unroll
    for (int i = 0; i < 2; i++){
#pragma unroll
        for (int j = 0; j < 2; j++){
            float v = vals[i][j];
            if (bias)  v += bias[n + j];
            if (act == 1) v = fmaxf(v, 0.f);
            if (resid) v += resid[(size_t)(m + i)*Nc + n + j];
            C[(size_t)(m + i)*Nc + n + j] = v;
        }
    }
}

// ---------------- GRU gates fused with FF LayerNorm ----------------
__global__ void k_gate_ln(const float* __restrict__ g, const float* __restrict__ be){
    int m = blockIdx.x, t = threadIdx.x;
    const float* gi = d_gi + (size_t)m*768;
    const float* gh = d_gh + (size_t)m*768;
    float ir = gi[t],        hr = gh[t];
    float iz = gi[256 + t],  hz = gh[256 + t];
    float in_ = gi[512 + t], hn = gh[512 + t];
    float r = 1.0f / (1.0f + __expf(-(ir + hr)));
    float z = 1.0f / (1.0f + __expf(-(iz + hz)));
    float nn = tanhf(fmaf(r, hn, in_));
    float hprev = d_S[(size_t)m*DIMD + t];
    float h = fmaf(1.0f - z, nn, z * hprev);
    d_S[(size_t)m*DIMD + t] = h;
    __shared__ float r1[DIMD], r2[DIMD];
    r1[t] = h; r2[t] = h*h;
    __syncthreads();
    for (int o = 128; o > 0; o >>= 1){
        if (t < o){ r1[t] += r1[t+o]; r2[t] += r2[t+o]; }
        __syncthreads();
    }
    float mu = r1[0] * (1.0f/DIMD);
    float rs = rsqrtf(r2[0] * (1.0f/DIMD) - mu*mu + EPSLN);
    d_lnb[(size_t)m*DIMD + t] = (h - mu)*rs*g[t] + be[t];
}

// ---------------- launch ----------------
extern "C" void kernel_launch(void* const* d_in, const int* in_sizes, int n_in,
                              void* d_out, int out_size){
    const float* x      = (const float*)d_in[0];
    const float* noise  = (const float*)d_in[1];
    const float* smu    = (const float*)d_in[2];
    const float* slsig  = (const float*)d_in[3];
    const float* Wq     = (const float*)d_in[4];
    const float* Wk     = (const float*)d_in[5];
    const float* Wv     = (const float*)d_in[6];
    const float* Wih    = (const float*)d_in[7];
    const float* Whh    = (const float*)d_in[8];
    const float* bih    = (const float*)d_in[9];
    const float* bhh    = (const float*)d_in[10];
    const float* W1     = (const float*)d_in[11];
    const float* b1     = (const float*)d_in[12];
    const float* W2     = (const float*)d_in[13];
    const float* b2     = (const float*)d_in[14];
    const float* g_in   = (const float*)d_in[15];
    const float* be_in  = (const float*)d_in[16];
    const float* g_sl   = (const float*)d_in[17];
    const float* be_sl  = (const float*)d_in[18];
    const float* g_ff   = (const float*)d_in[19];
    const float* be_ff  = (const float*)d_in[20];
    float* out = (float*)d_out;

    float *dS, *dLn, *dUpre, *dHff, *dGi, *dGh, *dWihv, *dMm, *dApre;
    cudaGetSymbolAddress((void**)&dS,    d_S);
    cudaGetSymbolAddress((void**)&dLn,   d_lnb);
    cudaGetSymbolAddress((void**)&dUpre, d_Upre);
    cudaGetSymbolAddress((void**)&dHff,  d_hff);
    cudaGetSymbolAddress((void**)&dGi,   d_gi);
    cudaGetSymbolAddress((void**)&dGh,   d_gh);
    cudaGetSymbolAddress((void**)&dWihv, d_Wihv);
    cudaGetSymbolAddress((void**)&dMm,   d_Mm);
    cudaGetSymbolAddress((void**)&dApre, d_Apre);

    k_precM   <<<DIMD,   DIMD>>>(Wq, Wk);
    k_precWihv<<<3*DIMD, DIMD>>>(Wih, Wv);
    k_init    <<<MROWS,  DIMD>>>(smu, noise, slsig);

    for (int it = 0; it < 3; it++){
        // slot LN -> Apre = LN(slots) @ M -> A/G/B
        k_lnrow<<<MROWS/8, 256>>>(dS, dLn, g_sl, be_sl);
        k_gemm <<<dim3(DIMD/32, MROWS/32, 1), 256>>>(dLn, dMm, nullptr, nullptr, dApre, DIMD, 0,
                                                     nullptr, nullptr, nullptr, nullptr);
        k_finA <<<MROWS, DIMD>>>(g_in, be_in);
        // streaming pass over x
        if (it == 0){
            k_flash<true><<<dim3(NCH, NBATCH), 128>>>(x);
            k_redC<<<NBATCH, DIMD>>>();
        } else {
            k_flash<false><<<dim3(NCH, NBATCH), 128>>>(x);
        }
        k_combine<<<MROWS, DIMD>>>(g_in, be_in);
        // GRU: gi = Upre @ Wihv^T + b_ih ; gh = S @ W_hh^T + b_hh (fused via z)
        k_gemm<<<dim3(768/32, MROWS/32, 2), 256>>>(dUpre, dWihv, bih, nullptr, dGi, 768, 0,
                                                   dS, Whh, bhh, dGh);
        k_gate_ln<<<MROWS, DIMD>>>(g_ff, be_ff);
        // FF
        k_gemm<<<dim3(DIMD/32, MROWS/32, 1), 256>>>(dLn, W1, b1, nullptr, dHff, DIMD, 1,
                                                    nullptr, nullptr, nullptr, nullptr);
        float* dst = (it == 2) ? out : dS;
        k_gemm<<<dim3(DIMD/32, MROWS/32, 1), 256>>>(dHff, W2, b2, dS, dst, DIMD, 0,
                                                    nullptr, nullptr, nullptr, nullptr);
    }
    (void)in_sizes; (void)n_in; (void)out_size;
}